// round 1
// baseline (speedup 1.0000x reference)
#include <cuda_runtime.h>
#include <math.h>

// Problem constants
#define NNODES 50000
#define CCH    128
#define PI_F   3.14159265358979323846f
#define R_CUT_F 5.0f

// Scratch (static device arrays: no allocation allowed)
__device__ float g_h[NNODES * CCH];          // silu(s@W1+b1), N x 128
__device__ float g_spass[NNODES * 3 * CCH];  // s_pass, N x 384

// ---------------------------------------------------------------------------
// Generic K=128 GEMM: out[n][j] = act(sum_k A[n][k]*W[k][j + blkY*128] + b[j+blkY*128])
// A: nrows x 128 (row stride 128). W row stride ldw. out row stride ldo.
// blockDim = 256, TILE_M = 64, k staged in chunks of 32 (48KB static smem).
// ---------------------------------------------------------------------------
__global__ void __launch_bounds__(256) gemm_k128(
    const float* __restrict__ A,
    const float* __restrict__ W, int ldw,
    const float* __restrict__ bias,
    float* __restrict__ out, int ldo,
    int nrows, int do_silu)
{
    __shared__ float As[64 * 128];   // 32 KB
    __shared__ float Ws[32 * 128];   // 16 KB

    const int colblk = blockIdx.y;
    W    += colblk * 128;
    bias += colblk * 128;
    out  += colblk * 128;

    const int row0 = blockIdx.x * 64;
    const int tid  = threadIdx.x;

    // Stage A tile (64 rows x 128 cols) as float4
    #pragma unroll
    for (int i = 0; i < 8; i++) {
        int lin = tid + i * 256;       // 0..2047 float4s
        int r   = lin >> 5;            // row within tile
        int c4  = lin & 31;            // float4 column
        float4 val = make_float4(0.f, 0.f, 0.f, 0.f);
        if (row0 + r < nrows)
            val = ((const float4*)(A + (size_t)(row0 + r) * 128))[c4];
        ((float4*)As)[lin] = val;
    }

    float acc[4][8];
    #pragma unroll
    for (int i = 0; i < 4; i++)
        #pragma unroll
        for (int j = 0; j < 8; j++) acc[i][j] = 0.f;

    const int ty = tid >> 4;   // 0..15 -> rows ty*4..ty*4+3
    const int tx = tid & 15;   // 0..15 -> cols tx*8..tx*8+7

    for (int kc = 0; kc < 128; kc += 32) {
        __syncthreads();
        // Stage W chunk (32 rows x 128 cols)
        #pragma unroll
        for (int i = 0; i < 4; i++) {
            int lin = tid + i * 256;   // 0..1023 float4s
            int kr  = lin >> 5;
            int c4  = lin & 31;
            ((float4*)Ws)[lin] = ((const float4*)(W + (size_t)(kc + kr) * ldw))[c4];
        }
        __syncthreads();

        #pragma unroll
        for (int kk = 0; kk < 32; kk++) {
            float a0 = As[(ty * 4 + 0) * 128 + kc + kk];
            float a1 = As[(ty * 4 + 1) * 128 + kc + kk];
            float a2 = As[(ty * 4 + 2) * 128 + kc + kk];
            float a3 = As[(ty * 4 + 3) * 128 + kc + kk];
            const float4 w0 = ((const float4*)(Ws + kk * 128))[tx * 2 + 0];
            const float4 w1 = ((const float4*)(Ws + kk * 128))[tx * 2 + 1];
            acc[0][0] = fmaf(a0, w0.x, acc[0][0]); acc[0][1] = fmaf(a0, w0.y, acc[0][1]);
            acc[0][2] = fmaf(a0, w0.z, acc[0][2]); acc[0][3] = fmaf(a0, w0.w, acc[0][3]);
            acc[0][4] = fmaf(a0, w1.x, acc[0][4]); acc[0][5] = fmaf(a0, w1.y, acc[0][5]);
            acc[0][6] = fmaf(a0, w1.z, acc[0][6]); acc[0][7] = fmaf(a0, w1.w, acc[0][7]);
            acc[1][0] = fmaf(a1, w0.x, acc[1][0]); acc[1][1] = fmaf(a1, w0.y, acc[1][1]);
            acc[1][2] = fmaf(a1, w0.z, acc[1][2]); acc[1][3] = fmaf(a1, w0.w, acc[1][3]);
            acc[1][4] = fmaf(a1, w1.x, acc[1][4]); acc[1][5] = fmaf(a1, w1.y, acc[1][5]);
            acc[1][6] = fmaf(a1, w1.z, acc[1][6]); acc[1][7] = fmaf(a1, w1.w, acc[1][7]);
            acc[2][0] = fmaf(a2, w0.x, acc[2][0]); acc[2][1] = fmaf(a2, w0.y, acc[2][1]);
            acc[2][2] = fmaf(a2, w0.z, acc[2][2]); acc[2][3] = fmaf(a2, w0.w, acc[2][3]);
            acc[2][4] = fmaf(a2, w1.x, acc[2][4]); acc[2][5] = fmaf(a2, w1.y, acc[2][5]);
            acc[2][6] = fmaf(a2, w1.z, acc[2][6]); acc[2][7] = fmaf(a2, w1.w, acc[2][7]);
            acc[3][0] = fmaf(a3, w0.x, acc[3][0]); acc[3][1] = fmaf(a3, w0.y, acc[3][1]);
            acc[3][2] = fmaf(a3, w0.z, acc[3][2]); acc[3][3] = fmaf(a3, w0.w, acc[3][3]);
            acc[3][4] = fmaf(a3, w1.x, acc[3][4]); acc[3][5] = fmaf(a3, w1.y, acc[3][5]);
            acc[3][6] = fmaf(a3, w1.z, acc[3][6]); acc[3][7] = fmaf(a3, w1.w, acc[3][7]);
        }
    }

    // Epilogue
    #pragma unroll
    for (int i = 0; i < 4; i++) {
        int r = row0 + ty * 4 + i;
        if (r < nrows) {
            #pragma unroll
            for (int j = 0; j < 8; j++) {
                float x = acc[i][j] + bias[tx * 8 + j];
                if (do_silu) x = x / (1.f + expf(-x));
                out[(size_t)r * ldo + tx * 8 + j] = x;
            }
        }
    }
}

// ---------------------------------------------------------------------------
// Edge kernel. blockDim = 128: thread c handles channel c for all 3 chunks
// (dv = col c, ds = col 128+c, drep = col 256+c). Wr columns live in registers
// (reused across all edges handled by the block). Grid-stride over edges.
// ---------------------------------------------------------------------------
__global__ void __launch_bounds__(128) edge_kernel(
    const void* __restrict__ edges_raw,
    const float* __restrict__ r_ij,
    const float* __restrict__ rhat,
    const float* __restrict__ spass,
    const float* __restrict__ v,
    const float* __restrict__ Wr,
    const float* __restrict__ br,
    float* __restrict__ s_out,
    float* __restrict__ v_out,
    int E)
{
    const int c = threadIdx.x;

    // Hoist the 3 Wr columns this thread needs into registers (60 regs)
    float wdv[20], wds[20], wdr[20];
    #pragma unroll
    for (int n = 0; n < 20; n++) {
        wdv[n] = Wr[n * 384 + c];
        wds[n] = Wr[n * 384 + 128 + c];
        wdr[n] = Wr[n * 384 + 256 + c];
    }
    const float bdv = br[c], bds = br[128 + c], bdr = br[256 + c];

    // Detect int64 vs int32 edge indices: real int64 values are < 50000;
    // int32 pairs read as u64 have the high index in the top 32 bits.
    const unsigned long long* e64 = (const unsigned long long*)edges_raw;
    const int*                e32 = (const int*)edges_raw;
    const bool is64 = (e64[0] < 50000ULL) && (e64[1] < 50000ULL) &&
                      (e64[2] < 50000ULL) && (e64[3] < 50000ULL);

    const float x_scale = PI_F / R_CUT_F;

    for (int e = blockIdx.x; e < E; e += gridDim.x) {
        long long dst, src;
        if (is64) { dst = (long long)e64[2 * e];  src = (long long)e64[2 * e + 1]; }
        else      { dst = e32[2 * e];             src = e32[2 * e + 1]; }

        const float r  = r_ij[e];
        const float rx = rhat[3 * e + 0];
        const float ry = rhat[3 * e + 1];
        const float rz = rhat[3 * e + 2];

        // RBF via Chebyshev recurrence: s_{n+1} = 2cos(x)*s_n - s_{n-1}
        const float x = x_scale * r;
        float s1, c1;
        __sincosf(x, &s1, &c1);
        const float fc    = 0.5f * (c1 + 1.f);   // fcut reuses cos(x)
        const float inv_r = 1.0f / r;
        const float c2    = 2.f * c1;

        float sprev = 0.f, scur = s1;
        float adv = 0.f, ads = 0.f, adr = 0.f;
        #pragma unroll
        for (int n = 0; n < 20; n++) {
            const float rb = scur * inv_r;
            adv = fmaf(rb, wdv[n], adv);
            ads = fmaf(rb, wds[n], ads);
            adr = fmaf(rb, wdr[n], adr);
            const float snext = fmaf(c2, scur, -sprev);
            sprev = scur; scur = snext;
        }
        adv = (adv + bdv) * fc;
        ads = (ads + bds) * fc;
        adr = (adr + bdr) * fc;

        // Gather s_pass[src] (coalesced: 128 consecutive floats per chunk)
        const float* spr = spass + (size_t)src * 384;
        const float dv = adv * spr[c];
        const float ds = ads * spr[128 + c];
        const float dr = adr * spr[256 + c];

        // Scatter
        atomicAdd(s_out + (size_t)dst * 128 + c, ds);

        const float* vr = v     + (size_t)src * 384;
        float*       vo = v_out + (size_t)dst * 384;
        atomicAdd(vo + c,       fmaf(vr[c],       dv, rx * dr));
        atomicAdd(vo + 128 + c, fmaf(vr[128 + c], dv, ry * dr));
        atomicAdd(vo + 256 + c, fmaf(vr[256 + c], dv, rz * dr));
    }
}

// ---------------------------------------------------------------------------
// kernel_launch
// Inputs (metadata order): s, v, edges, r_ij, r_ij_normalized,
//                          W1, b1, W2, b2, Wr, br
// Output: [s_out (N*128) | v_out (N*3*128)] float32
// ---------------------------------------------------------------------------
extern "C" void kernel_launch(void* const* d_in, const int* in_sizes, int n_in,
                              void* d_out, int out_size)
{
    const float* s     = (const float*)d_in[0];
    const float* v     = (const float*)d_in[1];
    const void*  edges = d_in[2];
    const float* r_ij  = (const float*)d_in[3];
    const float* rhat  = (const float*)d_in[4];
    const float* W1    = (const float*)d_in[5];
    const float* b1    = (const float*)d_in[6];
    const float* W2    = (const float*)d_in[7];
    const float* b2    = (const float*)d_in[8];
    const float* Wr    = (const float*)d_in[9];
    const float* br    = (const float*)d_in[10];

    const int N = in_sizes[0] / CCH;      // 50000
    const int E = in_sizes[3];            // 400000 (r_ij element count)

    float* out_s = (float*)d_out;
    float* out_v = out_s + (size_t)N * CCH;

    float* h_buf;
    float* sp_buf;
    cudaGetSymbolAddress((void**)&h_buf,  g_h);
    cudaGetSymbolAddress((void**)&sp_buf, g_spass);

    // Seed outputs with s and v (d_out is poisoned)
    cudaMemcpyAsync(out_s, s, (size_t)N * CCH * sizeof(float),
                    cudaMemcpyDeviceToDevice);
    cudaMemcpyAsync(out_v, v, (size_t)N * 3 * CCH * sizeof(float),
                    cudaMemcpyDeviceToDevice);

    // G1: h = silu(s @ W1 + b1)
    {
        dim3 grid((N + 63) / 64, 1);
        gemm_k128<<<grid, 256>>>(s, W1, 128, b1, h_buf, 128, N, 1);
    }
    // G2: s_pass = h @ W2 + b2   (3 column blocks of 128)
    {
        dim3 grid((N + 63) / 64, 3);
        gemm_k128<<<grid, 256>>>(h_buf, W2, 384, b2, sp_buf, 384, N, 0);
    }
    // Edge message + scatter
    {
        edge_kernel<<<4096, 128>>>(edges, r_ij, rhat, sp_buf, v,
                                   Wr, br, out_s, out_v, E);
    }
}

// round 2
// speedup vs baseline: 2.0981x; 2.0981x over previous
#include <cuda_runtime.h>
#include <math.h>

// Problem constants
#define NNODES 50000
#define CCH    128
#define PI_F   3.14159265358979323846f
#define R_CUT_F 5.0f

// Scratch (static device arrays: no allocation allowed)
__device__ float g_h[NNODES * CCH];          // silu(s@W1+b1), N x 128
__device__ float g_spass[NNODES * 3 * CCH];  // s_pass, N x 384

// ---------------------------------------------------------------------------
// GEMM K=128: out[r][j] = act(sum_k A[r][k] * W[k][colblk*128+j] + b[...])
// 128x128 output tile per block, 256 threads, 8x8 per-thread blocking,
// K staged in chunks of 16 with A tile transposed in smem.
// ---------------------------------------------------------------------------
__global__ void __launch_bounds__(256) gemm_v2(
    const float* __restrict__ A,
    const float* __restrict__ W, int ldw,
    const float* __restrict__ bias,
    float* __restrict__ out, int ldo,
    int nrows, int do_silu)
{
    __shared__ float As[16 * 128];   // [k][m] transposed, 8KB
    __shared__ float Ws[16 * 128];   // [k][n], 8KB

    const int colblk = blockIdx.y;
    W    += colblk * 128;
    bias += colblk * 128;
    out  += colblk * 128;

    const int row0 = blockIdx.x * 128;
    const int tid  = threadIdx.x;
    const int tx   = tid & 15;   // col group: cols tx*8 .. tx*8+7
    const int ty   = tid >> 4;   // row group: rows ty*8 .. ty*8+7

    float acc[8][8];
    #pragma unroll
    for (int i = 0; i < 8; i++)
        #pragma unroll
        for (int j = 0; j < 8; j++) acc[i][j] = 0.f;

    for (int k0 = 0; k0 < 128; k0 += 16) {
        __syncthreads();   // protect smem reads of previous chunk

        // Stage A tile (128 rows x 16 k) transposed: As[kk][m]
        #pragma unroll
        for (int i = 0; i < 2; i++) {
            int lin = tid + i * 256;          // 0..511 float4 reads
            int r   = lin >> 2;               // row in tile (0..127)
            int q   = lin & 3;                // k-float4 within chunk
            float4 av = make_float4(0.f, 0.f, 0.f, 0.f);
            if (row0 + r < nrows)
                av = *(const float4*)(A + (size_t)(row0 + r) * 128 + k0 + q * 4);
            As[(q * 4 + 0) * 128 + r] = av.x;
            As[(q * 4 + 1) * 128 + r] = av.y;
            As[(q * 4 + 2) * 128 + r] = av.z;
            As[(q * 4 + 3) * 128 + r] = av.w;
        }
        // Stage W chunk (16 rows x 128 cols) direct
        #pragma unroll
        for (int i = 0; i < 2; i++) {
            int lin = tid + i * 256;          // 0..511
            int kr  = lin >> 5;               // 0..15
            int c4  = lin & 31;
            *(float4*)(Ws + kr * 128 + c4 * 4) =
                *(const float4*)(W + (size_t)(k0 + kr) * ldw + c4 * 4);
        }
        __syncthreads();

        #pragma unroll
        for (int kk = 0; kk < 16; kk++) {
            float4 a0 = *(const float4*)(As + kk * 128 + ty * 8);
            float4 a1 = *(const float4*)(As + kk * 128 + ty * 8 + 4);
            float4 b0 = *(const float4*)(Ws + kk * 128 + tx * 8);
            float4 b1 = *(const float4*)(Ws + kk * 128 + tx * 8 + 4);
            float av[8] = {a0.x, a0.y, a0.z, a0.w, a1.x, a1.y, a1.z, a1.w};
            float bv[8] = {b0.x, b0.y, b0.z, b0.w, b1.x, b1.y, b1.z, b1.w};
            #pragma unroll
            for (int i = 0; i < 8; i++)
                #pragma unroll
                for (int j = 0; j < 8; j++)
                    acc[i][j] = fmaf(av[i], bv[j], acc[i][j]);
        }
    }

    // Epilogue
    #pragma unroll
    for (int i = 0; i < 8; i++) {
        int r = row0 + ty * 8 + i;
        if (r < nrows) {
            #pragma unroll
            for (int j = 0; j < 8; j++) {
                float x = acc[i][j] + bias[tx * 8 + j];
                if (do_silu) x = x / (1.f + __expf(-x));
                out[(size_t)r * ldo + tx * 8 + j] = x;
            }
        }
    }
}

// ---------------------------------------------------------------------------
// Vectorized global reduction: red.global.add.v4.f32 (sm_90+)
// ---------------------------------------------------------------------------
__device__ __forceinline__ void red_add_v4(float* p, float4 val) {
    asm volatile("red.global.add.v4.f32 [%0], {%1, %2, %3, %4};"
                 :: "l"(p), "f"(val.x), "f"(val.y), "f"(val.z), "f"(val.w)
                 : "memory");
}

// ---------------------------------------------------------------------------
// Edge kernel: 96 threads = 3 warps. Warp ch handles output chunk ch
// (0 = dv -> v_out, 1 = ds -> s_out, 2 = drep -> v_out). Each thread owns
// 4 consecutive channels (float4 everywhere). Wr columns in registers.
// ---------------------------------------------------------------------------
__global__ void __launch_bounds__(96) edge_kernel(
    const void* __restrict__ edges_raw,
    const float* __restrict__ r_ij,
    const float* __restrict__ rhat,
    const float* __restrict__ spass,
    const float* __restrict__ v,
    const float* __restrict__ Wr,
    const float* __restrict__ br,
    float* __restrict__ s_out,
    float* __restrict__ v_out,
    int E)
{
    const int ch   = threadIdx.x >> 5;   // chunk / warp id
    const int lane = threadIdx.x & 31;   // owns channels 4*lane..4*lane+3

    // Hoist this thread's 4 Wr columns into registers (80 regs)
    float4 w4[20];
    #pragma unroll
    for (int n = 0; n < 20; n++)
        w4[n] = *(const float4*)(Wr + n * 384 + ch * 128 + lane * 4);
    const float4 b4 = *(const float4*)(br + ch * 128 + lane * 4);

    // Detect int64 vs int32 edge indices
    const unsigned long long* e64 = (const unsigned long long*)edges_raw;
    const int*                e32 = (const int*)edges_raw;
    const bool is64 = (e64[0] < 50000ULL) && (e64[1] < 50000ULL) &&
                      (e64[2] < 50000ULL) && (e64[3] < 50000ULL);

    const float x_scale = PI_F / R_CUT_F;

    for (int e = blockIdx.x; e < E; e += gridDim.x) {
        long long dst, src;
        if (is64) { dst = (long long)e64[2 * e];  src = (long long)e64[2 * e + 1]; }
        else      { dst = e32[2 * e];             src = e32[2 * e + 1]; }

        const float r  = r_ij[e];
        const float rx = rhat[3 * e + 0];
        const float ry = rhat[3 * e + 1];
        const float rz = rhat[3 * e + 2];

        // sin(n*x) recurrence; inv_r factored out of the dot product
        const float x = x_scale * r;
        float s1, c1;
        __sincosf(x, &s1, &c1);
        const float fc    = 0.5f * (c1 + 1.f);
        const float inv_r = 1.0f / r;
        const float c2    = 2.f * c1;

        float sprev = 0.f, scur = s1;
        float4 acc = make_float4(0.f, 0.f, 0.f, 0.f);
        #pragma unroll
        for (int n = 0; n < 20; n++) {
            acc.x = fmaf(scur, w4[n].x, acc.x);
            acc.y = fmaf(scur, w4[n].y, acc.y);
            acc.z = fmaf(scur, w4[n].z, acc.z);
            acc.w = fmaf(scur, w4[n].w, acc.w);
            const float snext = fmaf(c2, scur, -sprev);
            sprev = scur; scur = snext;
        }
        const float g = inv_r * fc;
        float4 a4;
        a4.x = fmaf(acc.x, g, b4.x * fc);
        a4.y = fmaf(acc.y, g, b4.y * fc);
        a4.z = fmaf(acc.z, g, b4.z * fc);
        a4.w = fmaf(acc.w, g, b4.w * fc);

        // Gather s_pass[src] chunk (coalesced float4)
        const float4* sprow = (const float4*)(spass + (size_t)src * 384);
        const float4  sp4   = sprow[ch * 32 + lane];
        float4 coef;
        coef.x = a4.x * sp4.x; coef.y = a4.y * sp4.y;
        coef.z = a4.z * sp4.z; coef.w = a4.w * sp4.w;

        if (ch == 0) {
            // delta_v += v[src] * dv
            const float4* vrow = (const float4*)(v + (size_t)src * 384);
            float* vobase = v_out + (size_t)dst * 384;
            #pragma unroll
            for (int d = 0; d < 3; d++) {
                float4 vv = vrow[d * 32 + lane];
                float4 out4;
                out4.x = vv.x * coef.x; out4.y = vv.y * coef.y;
                out4.z = vv.z * coef.z; out4.w = vv.w * coef.w;
                red_add_v4(vobase + d * 128 + lane * 4, out4);
            }
        } else if (ch == 1) {
            red_add_v4(s_out + (size_t)dst * 128 + lane * 4, coef);
        } else {
            // delta_v += rhat[:,None] * drep
            float* vobase = v_out + (size_t)dst * 384;
            float rh[3] = {rx, ry, rz};
            #pragma unroll
            for (int d = 0; d < 3; d++) {
                float4 out4;
                out4.x = rh[d] * coef.x; out4.y = rh[d] * coef.y;
                out4.z = rh[d] * coef.z; out4.w = rh[d] * coef.w;
                red_add_v4(vobase + d * 128 + lane * 4, out4);
            }
        }
    }
}

// ---------------------------------------------------------------------------
// kernel_launch
// Inputs: s, v, edges, r_ij, r_ij_normalized, W1, b1, W2, b2, Wr, br
// Output: [s_out (N*128) | v_out (N*3*128)] float32
// ---------------------------------------------------------------------------
extern "C" void kernel_launch(void* const* d_in, const int* in_sizes, int n_in,
                              void* d_out, int out_size)
{
    const float* s     = (const float*)d_in[0];
    const float* v     = (const float*)d_in[1];
    const void*  edges = d_in[2];
    const float* r_ij  = (const float*)d_in[3];
    const float* rhat  = (const float*)d_in[4];
    const float* W1    = (const float*)d_in[5];
    const float* b1    = (const float*)d_in[6];
    const float* W2    = (const float*)d_in[7];
    const float* b2    = (const float*)d_in[8];
    const float* Wr    = (const float*)d_in[9];
    const float* br    = (const float*)d_in[10];

    const int N = in_sizes[0] / CCH;      // 50000
    const int E = in_sizes[3];            // 400000

    float* out_s = (float*)d_out;
    float* out_v = out_s + (size_t)N * CCH;

    float* h_buf;
    float* sp_buf;
    cudaGetSymbolAddress((void**)&h_buf,  g_h);
    cudaGetSymbolAddress((void**)&sp_buf, g_spass);

    // Seed outputs with s and v (d_out is poisoned)
    cudaMemcpyAsync(out_s, s, (size_t)N * CCH * sizeof(float),
                    cudaMemcpyDeviceToDevice);
    cudaMemcpyAsync(out_v, v, (size_t)N * 3 * CCH * sizeof(float),
                    cudaMemcpyDeviceToDevice);

    // G1: h = silu(s @ W1 + b1)
    {
        dim3 grid((N + 127) / 128, 1);
        gemm_v2<<<grid, 256>>>(s, W1, 128, b1, h_buf, 128, N, 1);
    }
    // G2: s_pass = h @ W2 + b2   (3 column blocks of 128)
    {
        dim3 grid((N + 127) / 128, 3);
        gemm_v2<<<grid, 256>>>(h_buf, W2, 384, b2, sp_buf, 384, N, 0);
    }
    // Edge message + scatter
    {
        edge_kernel<<<8192, 96>>>(edges, r_ij, rhat, sp_buf, v,
                                  Wr, br, out_s, out_v, E);
    }
}